// round 14
// baseline (speedup 1.0000x reference)
#include <cuda_runtime.h>
#include <cuda_fp16.h>
#include <mma.h>
#include <cstdint>

using namespace nvcuda;

#define Ecfg 1024
#define Hh   16
#define HKV  4
#define Dd   64

#define BM  128
#define BN  128
#define BKg 64
#define LDA 72    // halves (64 + 8 pad)
#define LDK 72    // halves
#define LDC 132   // fp32 staging stride (128 + 4 pad)
#define NSTG 3    // cp.async pipeline stages (GEMM)

// ---------------- scratch (device globals) ----------------
__device__ __half g_qt [2 * 16 * 2048 * 64];
__device__ __half g_kt [2 * 4  * 2048 * 64];
__device__ __half g_vt [2 * 4  * 2048 * 64];
__device__ __half g_y  [2 * 2048 * 1024];
__device__ __half g_xh [2 * 2048 * 1024];
__device__ __half g_wqh[1024 * 1024];
__device__ __half g_wkh[256 * 1024];
__device__ __half g_wvh[256 * 1024];
__device__ __half g_wph[1024 * 1024];

// ---------------- cp.async helpers ----------------
__device__ __forceinline__ void cp16(void* smem_dst, const void* gsrc) {
    uint32_t s = (uint32_t)__cvta_generic_to_shared(smem_dst);
    asm volatile("cp.async.cg.shared.global [%0], [%1], 16;\n" :: "r"(s), "l"(gsrc));
}
#define CP_COMMIT() asm volatile("cp.async.commit_group;\n" ::: "memory")
#define CP_WAIT1()  asm volatile("cp.async.wait_group 1;\n" ::: "memory")
#define CP_WAIT0()  asm volatile("cp.async.wait_group 0;\n" ::: "memory")

__device__ __forceinline__ uint32_t smem_u32(const void* p) {
    return (uint32_t)__cvta_generic_to_shared(p);
}

// ---------------- mma / ldmatrix primitives ----------------
__device__ __forceinline__ void mma16816(float d[4], const uint32_t a[4],
                                         uint32_t b0, uint32_t b1) {
    asm volatile(
        "mma.sync.aligned.m16n8k16.row.col.f32.f16.f16.f32 "
        "{%0,%1,%2,%3}, {%4,%5,%6,%7}, {%8,%9}, {%0,%1,%2,%3};"
        : "+f"(d[0]), "+f"(d[1]), "+f"(d[2]), "+f"(d[3])
        : "r"(a[0]), "r"(a[1]), "r"(a[2]), "r"(a[3]), "r"(b0), "r"(b1));
}
__device__ __forceinline__ void ldm4(uint32_t r[4], uint32_t addr) {
    asm volatile("ldmatrix.sync.aligned.m8n8.x4.shared.b16 {%0,%1,%2,%3}, [%4];"
                 : "=r"(r[0]), "=r"(r[1]), "=r"(r[2]), "=r"(r[3]) : "r"(addr));
}
__device__ __forceinline__ void ldm4t(uint32_t r[4], uint32_t addr) {
    asm volatile("ldmatrix.sync.aligned.m8n8.x4.trans.shared.b16 {%0,%1,%2,%3}, [%4];"
                 : "=r"(r[0]), "=r"(r[1]), "=r"(r[2]), "=r"(r[3]) : "r"(addr));
}

// ---------------- fast exp2 (no MUFU) ----------------
__device__ __forceinline__ float fast_exp2(float x) {
    float t = x + 12582912.0f;
    int   ei = __float_as_int(t) - 0x4B400000;
    float f = x - (t - 12582912.0f);
    float e = fmaf(f, 0.0013333558f, 0.0096181291f);
    e = fmaf(f, e, 0.0555041087f);
    e = fmaf(f, e, 0.2402265070f);
    e = fmaf(f, e, 0.6931471806f);
    e = fmaf(f, e, 1.0f);
    return __int_as_float(__float_as_int(e) + (ei << 23));
}
#define LOG2E_F  1.4426950408889634f
#define NBIAS_F  (-11.541560327111707f)

// ---------------- fused fp16 convert of x + all weights (1 launch) ----------------
#define N4_WQ 262144
#define N4_WK 65536
#define N4_WV 65536
#define N4_WP 262144
__global__ void cvt_all(const float* __restrict__ x,  const float* __restrict__ wq,
                        const float* __restrict__ wk, const float* __restrict__ wv,
                        const float* __restrict__ wp,
                        __half* __restrict__ xo, __half* __restrict__ wqo,
                        __half* __restrict__ wko, __half* __restrict__ wvo,
                        __half* __restrict__ wpo, int n4x) {
    int i = blockIdx.x * blockDim.x + threadIdx.x;
    const float4* s; __half* d; int j;
    if (i < n4x) { s = (const float4*)x; d = xo; j = i; }
    else {
        i -= n4x;
        if (i < N4_WQ)                          { s = (const float4*)wq; d = wqo; j = i; }
        else if (i < N4_WQ + N4_WK)             { s = (const float4*)wk; d = wko; j = i - N4_WQ; }
        else if (i < N4_WQ + N4_WK + N4_WV)     { s = (const float4*)wv; d = wvo; j = i - N4_WQ - N4_WK; }
        else if (i < N4_WQ + N4_WK + N4_WV + N4_WP) { s = (const float4*)wp; d = wpo; j = i - N4_WQ - N4_WK - N4_WV; }
        else return;
    }
    float4 v = s[j];
    __half2 h0 = __floats2half2_rn(v.x, v.y);
    __half2 h1 = __floats2half2_rn(v.z, v.w);
    *reinterpret_cast<__half2*>(&d[j * 4])     = h0;
    *reinterpret_cast<__half2*>(&d[j * 4 + 2]) = h1;
}

// ================= FP16 GEMM mainloop, cp.async 3-stage, BK=64 =================
// BM=BN=128, 256 thr = 8 warps (2M x 4N), warp tile 64x32. Leaves acc in registers.
// NO trailing sync — caller must __syncthreads() before reusing smem.
__device__ __forceinline__ void gemm_mainloop(
    const __half* __restrict__ A, const __half* __restrict__ W,
    int K, int m0, int n0,
    wmma::fragment<wmma::accumulator, 16, 16, 16, float> (&acc)[4][2]) {
    extern __shared__ __half smh[];
    __half* As = smh;                          // NSTG * 128 * LDA
    __half* Ws = smh + NSTG * BM * LDA;        // NSTG * 128 * LDA
    const int tid = threadIdx.x;
    const int warp = tid >> 5;
    const int wm = warp >> 2;
    const int wn = warp & 3;

#pragma unroll
    for (int i = 0; i < 4; i++)
#pragma unroll
        for (int j = 0; j < 2; j++) wmma::fill_fragment(acc[i][j], 0.f);

    const __half* Ab = A + (size_t)m0 * K;
    const __half* Wb = W + (size_t)n0 * K;

#define LOAD_SLAB(it, buf)                                                      \
    {                                                                           \
        const int k0 = (it) << 6;                                               \
        __half* ad = As + (buf) * BM * LDA;                                     \
        __half* wd = Ws + (buf) * BN * LDA;                                     \
        _Pragma("unroll")                                                       \
        for (int i = 0; i < 4; i++) {                                           \
            int ch = tid + i * 256;          /* 0..1023 */                      \
            int r = ch >> 3, c8 = (ch & 7) << 3;                                \
            cp16(ad + r * LDA + c8, Ab + (size_t)r * K + k0 + c8);              \
            cp16(wd + r * LDA + c8, Wb + (size_t)r * K + k0 + c8);              \
        }                                                                       \
    }

    const int nIter = K >> 6;
    LOAD_SLAB(0, 0); CP_COMMIT();
    LOAD_SLAB(1, 1); CP_COMMIT();

    int buf = 0;
    for (int it = 0; it < nIter; ++it) {
        if (it + 1 < nIter) CP_WAIT1(); else CP_WAIT0();
        __syncthreads();
        if (it + 2 < nIter) {
            int nb = buf + 2; if (nb >= NSTG) nb -= NSTG;
            LOAD_SLAB(it + 2, nb); CP_COMMIT();
        }
        const __half* as = As + buf * BM * LDA;
        const __half* ws = Ws + buf * BN * LDA;
#pragma unroll
        for (int kk = 0; kk < BKg; kk += 16) {
            wmma::fragment<wmma::matrix_a, 16, 16, 16, __half, wmma::row_major> a[4];
            wmma::fragment<wmma::matrix_b, 16, 16, 16, __half, wmma::col_major> b[2];
#pragma unroll
            for (int i = 0; i < 4; i++)
                wmma::load_matrix_sync(a[i], &as[(wm * 64 + i * 16) * LDA + kk], LDA);
#pragma unroll
            for (int j = 0; j < 2; j++)
                wmma::load_matrix_sync(b[j], &ws[(wn * 32 + j * 16) * LDA + kk], LDA);
#pragma unroll
            for (int i = 0; i < 4; i++)
#pragma unroll
                for (int j = 0; j < 2; j++)
                    wmma::mma_sync(acc[i][j], a[i], b[j], acc[i][j]);
        }
        if (++buf == NSTG) buf = 0;
    }
#undef LOAD_SLAB
}

// output projection: plain fp32 epilogue
__global__ __launch_bounds__(256) void gemm_proj(
    const __half* __restrict__ A, const __half* __restrict__ W, float* __restrict__ C, int K) {
    wmma::fragment<wmma::accumulator, 16, 16, 16, float> acc[4][2];
    const int m0 = blockIdx.y * BM, n0 = blockIdx.x * BN;
    gemm_mainloop(A, W, K, m0, n0, acc);
    __syncthreads();
    const int warp = threadIdx.x >> 5;
    const int wm = warp >> 2, wn = warp & 3;
#pragma unroll
    for (int i = 0; i < 4; i++)
#pragma unroll
        for (int j = 0; j < 2; j++)
            wmma::store_matrix_sync(&C[(size_t)(m0 + wm * 64 + i * 16) * Ecfg + n0 + wn * 32 + j * 16],
                                    acc[i][j], Ecfg, wmma::mem_row_major);
}

// fused QKV GEMM + rope/rmsnorm/V-gate epilogue -> writes fp16 qt/kt/vt directly.
// 12 n-tiles: 8 Q (type 0), 2 K (type 1), 2 V (type 2). Each 128-col tile = 2 heads.
__global__ __launch_bounds__(256) void gemm_qkv(
    const __half* __restrict__ xh,
    const __half* __restrict__ Wq, const __half* __restrict__ Wk, const __half* __restrict__ Wv,
    __half* __restrict__ qt, __half* __restrict__ kt, __half* __restrict__ vt,
    const float* __restrict__ x, const float* __restrict__ ve,
    const float* __restrict__ cosb, const float* __restrict__ sinb,
    const float* __restrict__ Wgate, int K, int T) {
    extern __shared__ __half smh[];
    const int ng = blockIdx.x * BN;
    const __half* W; int n0, type;
    if (ng < 1024)      { W = Wq; n0 = ng;        type = 0; }
    else if (ng < 1280) { W = Wk; n0 = ng - 1024; type = 1; }
    else                { W = Wv; n0 = ng - 1280; type = 2; }
    const int m0 = blockIdx.y * BM;

    wmma::fragment<wmma::accumulator, 16, 16, 16, float> acc[4][2];
    gemm_mainloop(xh, W, K, m0, n0, acc);
    __syncthreads();   // all warps done with pipeline smem

    // stage fp32 accumulators to smem (67.6 KB <= pipeline smem)
    float* S = reinterpret_cast<float*>(smh);
    const int warp = threadIdx.x >> 5, lane = threadIdx.x & 31;
    const int wm = warp >> 2, wn = warp & 3;
#pragma unroll
    for (int i = 0; i < 4; i++)
#pragma unroll
        for (int j = 0; j < 2; j++)
            wmma::store_matrix_sync(&S[(wm * 64 + i * 16) * LDC + wn * 32 + j * 16],
                                    acc[i][j], LDC, wmma::mem_row_major);
    __syncthreads();

    // 256 (row, head) tasks over 8 warps; lane = d in [0,32)
    const int hbase = n0 >> 6;
    for (int task = warp; task < 256; task += 8) {
        const int r = task >> 1, hh = task & 1;
        const int mt = m0 + r;
        const int bb = mt / T;
        const int t = mt - bb * T;
        float v1 = S[r * LDC + hh * 64 + lane];
        float v2 = S[r * LDC + hh * 64 + 32 + lane];
        if (type == 2) {
            // V: v + 2*sigmoid(x[:32] @ Wgate[kvh]) * ve
            const int kvh = hbase + hh;
            float g = x[(size_t)mt * Ecfg + lane] * Wgate[kvh * 32 + lane];
#pragma unroll
            for (int o = 16; o; o >>= 1) g += __shfl_xor_sync(0xffffffffu, g, o);
            float gate = 2.f / (1.f + __expf(-g));
            const float* vep = ve + ((size_t)mt * HKV + kvh) * 64;
            __half* d = vt + (((size_t)bb * HKV + kvh) * T + t) * 64;
            d[lane]      = __float2half(v1 + gate * vep[lane]);
            d[32 + lane] = __float2half(v2 + gate * vep[32 + lane]);
        } else {
            // Q/K: rope + rmsnorm (Q additionally pre-scaled by 1/8)
            float c = cosb[(size_t)t * 32 + lane];
            float s = sinb[(size_t)t * 32 + lane];
            float r1 = v1 * c + v2 * s;
            float r2 = v2 * c - v1 * s;
            float ss = r1 * r1 + r2 * r2;
#pragma unroll
            for (int o = 16; o; o >>= 1) ss += __shfl_xor_sync(0xffffffffu, ss, o);
            float inv = rsqrtf(ss * (1.f / 64.f) + 1.1920929e-07f);
            __half* d;
            if (type == 0) {
                inv *= 0.125f;
                const int h = hbase + hh;
                d = qt + (((size_t)bb * Hh + h) * T + t) * 64;
            } else {
                const int kvh = hbase + hh;
                d = kt + (((size_t)bb * HKV + kvh) * T + t) * 64;
            }
            d[lane]      = __float2half(r1 * inv);
            d[32 + lane] = __float2half(r2 * inv);
        }
    }
}

// ================ flash attention: raw mma + register softmax (R13 exact) ================
__global__ __launch_bounds__(128) void attn_mma(
    const __half* __restrict__ q, const __half* __restrict__ k,
    const __half* __restrict__ v, __half* __restrict__ out,
    const int* __restrict__ wptr, int T) {
    extern __shared__ __half smh[];
    __half* Ks = smh;                  // 2 * 64 * LDK
    __half* Vs = smh + 2 * 64 * LDK;   // 2 * 64 * LDK
    const uint32_t ks0 = smem_u32(Ks);
    const uint32_t vs0 = smem_u32(Vs);

    const int qtile = blockIdx.x, h = blockIdx.y, b = blockIdx.z;
    const int W = wptr[0];
    const int tid = threadIdx.x;
    const int warp = tid >> 5, lane = tid & 31;
    const int qbase = qtile * 128;
    const int rq = lane >> 2;
    const int qc = (lane & 3) << 1;

    const int krow = ((lane >> 4) << 3) + (lane & 7);
    const int kcol = ((lane >> 3) & 1) << 3;
    const int vrow = (((lane >> 3) & 1) << 3) + (lane & 7);
    const int vcol = (lane >> 4) << 3;

    uint32_t qa[2][4][4];
#pragma unroll
    for (int i = 0; i < 2; i++) {
        const __half* q0 = q + ((size_t)(b * Hh + h) * T + qbase + warp * 32 + i * 16 + rq) * Dd;
        const __half* q8 = q0 + 8 * Dd;
#pragma unroll
        for (int t = 0; t < 4; t++) {
            qa[i][t][0] = *reinterpret_cast<const uint32_t*>(q0 + t * 16 + qc);
            qa[i][t][1] = *reinterpret_cast<const uint32_t*>(q8 + t * 16 + qc);
            qa[i][t][2] = *reinterpret_cast<const uint32_t*>(q0 + t * 16 + 8 + qc);
            qa[i][t][3] = *reinterpret_cast<const uint32_t*>(q8 + t * 16 + 8 + qc);
        }
    }

    float o[2][8][4];
#pragma unroll
    for (int i = 0; i < 2; i++)
#pragma unroll
        for (int j = 0; j < 8; j++)
#pragma unroll
            for (int c = 0; c < 4; c++) o[i][j][c] = 0.f;
    float lsum[2][2] = {{0.f, 0.f}, {0.f, 0.f}};

    const int hkv = h >> 2;
    const __half* kb = k + (size_t)(b * HKV + hkv) * T * Dd;
    const __half* vb = v + (size_t)(b * HKV + hkv) * T * Dd;
    int kmin = qbase - W; if (kmin < 0) kmin = 0;
    const int t0 = kmin >> 6;
    const int ktend = 2 * qtile + 1;

#define LOAD_KV(kt, buf)                                                        \
    {                                                                           \
        const __half* kp = kb + (size_t)(kt) * 64 * Dd;                         \
        const __half* vp = vb + (size_t)(kt) * 64 * Dd;                         \
        __half* kd = Ks + (buf) * 64 * LDK;                                     \
        __half* vd = Vs + (buf) * 64 * LDK;                                     \
        _Pragma("unroll")                                                       \
        for (int i = 0; i < 4; i++) {                                           \
            int ch = tid + i * 128;                                             \
            int r = ch >> 3, c8 = (ch & 7) << 3;                                \
            cp16(kd + r * LDK + c8, kp + r * 64 + c8);                          \
            cp16(vd + r * LDK + c8, vp + r * 64 + c8);                          \
        }                                                                       \
    }

    LOAD_KV(t0, 0); CP_COMMIT();

    for (int kt = t0; kt <= ktend; ++kt) {
        const int buf = (kt - t0) & 1;
        if (kt < ktend) { LOAD_KV(kt + 1, buf ^ 1); CP_COMMIT(); CP_WAIT1(); }
        else CP_WAIT0();
        __syncthreads();
        const uint32_t ksb = ks0 + buf * 64 * LDK * 2;
        const uint32_t vsb = vs0 + buf * 64 * LDK * 2;

#pragma unroll
        for (int t = 0; t < 4; t++) {
            float s[2][2][4];
#pragma unroll
            for (int i = 0; i < 2; i++)
#pragma unroll
                for (int jj = 0; jj < 2; jj++)
#pragma unroll
                    for (int c = 0; c < 4; c++) s[i][jj][c] = 0.f;
#pragma unroll
            for (int kd = 0; kd < 4; kd++) {
                uint32_t kbf[4];
                ldm4(kbf, ksb + (uint32_t)(((t * 16 + krow) * LDK + kd * 16 + kcol) * 2));
                mma16816(s[0][0], qa[0][kd], kbf[0], kbf[1]);
                mma16816(s[0][1], qa[0][kd], kbf[2], kbf[3]);
                mma16816(s[1][0], qa[1][kd], kbf[0], kbf[1]);
                mma16816(s[1][1], qa[1][kd], kbf[2], kbf[3]);
            }
            uint32_t pa[2][4];
#pragma unroll
            for (int i = 0; i < 2; i++) {
                const int row0 = qbase + warp * 32 + i * 16 + rq;
#pragma unroll
                for (int jj = 0; jj < 2; jj++) {
                    const int colb = (kt << 6) + t * 16 + jj * 8 + qc;
#pragma unroll
                    for (int c = 0; c < 4; c++) {
                        const int row = row0 + ((c >> 1) << 3);
                        const int col = colb + (c & 1);
                        float pv = 0.f;
                        if (col <= row && col >= row - W) {
                            pv = fast_exp2(fmaf(s[i][jj][c], LOG2E_F, NBIAS_F));
                            lsum[i][c >> 1] += pv;
                        }
                        s[i][jj][c] = pv;
                    }
                    __half2 lo = __floats2half2_rn(s[i][jj][0], s[i][jj][1]);
                    __half2 hi = __floats2half2_rn(s[i][jj][2], s[i][jj][3]);
                    pa[i][jj * 2 + 0] = *reinterpret_cast<uint32_t*>(&lo);
                    pa[i][jj * 2 + 1] = *reinterpret_cast<uint32_t*>(&hi);
                }
            }
#pragma unroll
            for (int jdp = 0; jdp < 4; jdp++) {
                uint32_t vbf[4];
                ldm4t(vbf, vsb + (uint32_t)(((t * 16 + vrow) * LDK + jdp * 16 + vcol) * 2));
                mma16816(o[0][jdp * 2 + 0], pa[0], vbf[0], vbf[1]);
                mma16816(o[0][jdp * 2 + 1], pa[0], vbf[2], vbf[3]);
                mma16816(o[1][jdp * 2 + 0], pa[1], vbf[0], vbf[1]);
                mma16816(o[1][jdp * 2 + 1], pa[1], vbf[2], vbf[3]);
            }
        }
        __syncthreads();
    }
#undef LOAD_KV

#pragma unroll
    for (int i = 0; i < 2; i++) {
#pragma unroll
        for (int rh = 0; rh < 2; rh++) {
            float l = lsum[i][rh];
            l += __shfl_xor_sync(0xffffffffu, l, 1);
            l += __shfl_xor_sync(0xffffffffu, l, 2);
            const float inv = 1.f / l;
            const int qrow = qbase + warp * 32 + i * 16 + rq + rh * 8;
            __half* op = out + ((size_t)(b * T + qrow) * Hh + h) * Dd + qc;
#pragma unroll
            for (int jd = 0; jd < 8; jd++) {
                __half2 hv = __floats2half2_rn(o[i][jd][rh * 2] * inv,
                                               o[i][jd][rh * 2 + 1] * inv);
                *reinterpret_cast<__half2*>(op + jd * 8) = hv;
            }
        }
    }
}

// ---------------- launch ----------------
extern "C" void kernel_launch(void* const* d_in, const int* in_sizes, int n_in,
                              void* d_out, int out_size) {
    const float* x     = (const float*)d_in[0];
    const float* ve    = (const float*)d_in[1];
    const float* cosb  = (const float*)d_in[2];
    const float* sinb  = (const float*)d_in[3];
    const float* Wq    = (const float*)d_in[4];
    const float* Wk    = (const float*)d_in[5];
    const float* Wv    = (const float*)d_in[6];
    const float* Wproj = (const float*)d_in[7];
    const float* Wgate = (const float*)d_in[8];
    const int*   wsz   = (const int*)d_in[9];

    int T = in_sizes[2] / 32;
    int B = in_sizes[0] / (T * Ecfg);
    int M = B * T;

    __half *qt, *kt, *vt, *y, *xh, *wqh, *wkh, *wvh, *wph;
    cudaGetSymbolAddress((void**)&qt,   g_qt);
    cudaGetSymbolAddress((void**)&kt,   g_kt);
    cudaGetSymbolAddress((void**)&vt,   g_vt);
    cudaGetSymbolAddress((void**)&y,    g_y);
    cudaGetSymbolAddress((void**)&xh,   g_xh);
    cudaGetSymbolAddress((void**)&wqh,  g_wqh);
    cudaGetSymbolAddress((void**)&wkh,  g_wkh);
    cudaGetSymbolAddress((void**)&wvh,  g_wvh);
    cudaGetSymbolAddress((void**)&wph,  g_wph);

    const int gemm_smem = NSTG * (BM + BN) * LDA * 2;   // 110592 (>= 128*LDC*4 staging)
    const int attn_smem = 4 * 64 * LDK * 2;             // 36864
    cudaFuncSetAttribute(gemm_qkv,  cudaFuncAttributeMaxDynamicSharedMemorySize, gemm_smem);
    cudaFuncSetAttribute(gemm_proj, cudaFuncAttributeMaxDynamicSharedMemorySize, gemm_smem);
    cudaFuncSetAttribute(attn_mma,  cudaFuncAttributeMaxDynamicSharedMemorySize, attn_smem);

    {
        int n4x = M * Ecfg / 4;
        int total = n4x + N4_WQ + N4_WK + N4_WV + N4_WP;
        cvt_all<<<(total + 255) / 256, 256>>>(x, Wq, Wk, Wv, Wproj,
                                              xh, wqh, wkh, wvh, wph, n4x);
    }

    gemm_qkv<<<dim3(1536 / BN, M / BM), 256, gemm_smem>>>(
        xh, wqh, wkh, wvh, qt, kt, vt, x, ve, cosb, sinb, Wgate, Ecfg, T);

    attn_mma<<<dim3(T / 128, Hh, B), 128, attn_smem>>>(qt, kt, vt, y, wsz, T);

    gemm_proj<<<dim3(Ecfg / BN, M / BM), 256, gemm_smem>>>(y, wph, (float*)d_out, Ecfg);
}

// round 15
// speedup vs baseline: 1.1025x; 1.1025x over previous
#include <cuda_runtime.h>
#include <cuda_fp16.h>
#include <mma.h>
#include <cstdint>

using namespace nvcuda;

#define Ecfg 1024
#define Hh   16
#define HKV  4
#define Dd   64

#define BM  128
#define BN  128
#define BKg 64
#define LDA 72    // halves (64 + 8 pad)
#define LDK 72    // halves
#define NSTG 3    // cp.async pipeline stages (GEMM)

// ---------------- scratch (device globals) ----------------
__device__ float  g_qraw[2 * 2048 * 1024];
__device__ float  g_kraw[2 * 2048 * 256];
__device__ float  g_vraw[2 * 2048 * 256];
__device__ __half g_qt [2 * 16 * 2048 * 64];
__device__ __half g_kt [2 * 4  * 2048 * 64];
__device__ __half g_vt [2 * 4  * 2048 * 64];
__device__ __half g_y  [2 * 2048 * 1024];
__device__ __half g_xh [2 * 2048 * 1024];
__device__ __half g_wqh[1024 * 1024];
__device__ __half g_wkh[256 * 1024];
__device__ __half g_wvh[256 * 1024];
__device__ __half g_wph[1024 * 1024];

// ---------------- cp.async helpers ----------------
__device__ __forceinline__ void cp16(void* smem_dst, const void* gsrc) {
    uint32_t s = (uint32_t)__cvta_generic_to_shared(smem_dst);
    asm volatile("cp.async.cg.shared.global [%0], [%1], 16;\n" :: "r"(s), "l"(gsrc));
}
#define CP_COMMIT() asm volatile("cp.async.commit_group;\n" ::: "memory")
#define CP_WAIT1()  asm volatile("cp.async.wait_group 1;\n" ::: "memory")
#define CP_WAIT0()  asm volatile("cp.async.wait_group 0;\n" ::: "memory")

__device__ __forceinline__ uint32_t smem_u32(const void* p) {
    return (uint32_t)__cvta_generic_to_shared(p);
}

// ---------------- mma / ldmatrix primitives ----------------
__device__ __forceinline__ void mma16816(float d[4], const uint32_t a[4],
                                         uint32_t b0, uint32_t b1) {
    asm volatile(
        "mma.sync.aligned.m16n8k16.row.col.f32.f16.f16.f32 "
        "{%0,%1,%2,%3}, {%4,%5,%6,%7}, {%8,%9}, {%0,%1,%2,%3};"
        : "+f"(d[0]), "+f"(d[1]), "+f"(d[2]), "+f"(d[3])
        : "r"(a[0]), "r"(a[1]), "r"(a[2]), "r"(a[3]), "r"(b0), "r"(b1));
}
__device__ __forceinline__ void ldm4(uint32_t r[4], uint32_t addr) {
    asm volatile("ldmatrix.sync.aligned.m8n8.x4.shared.b16 {%0,%1,%2,%3}, [%4];"
                 : "=r"(r[0]), "=r"(r[1]), "=r"(r[2]), "=r"(r[3]) : "r"(addr));
}
__device__ __forceinline__ void ldm4t(uint32_t r[4], uint32_t addr) {
    asm volatile("ldmatrix.sync.aligned.m8n8.x4.trans.shared.b16 {%0,%1,%2,%3}, [%4];"
                 : "=r"(r[0]), "=r"(r[1]), "=r"(r[2]), "=r"(r[3]) : "r"(addr));
}

// ---------------- fast exp2 (no MUFU) ----------------
__device__ __forceinline__ float fast_exp2(float x) {
    float t = x + 12582912.0f;
    int   ei = __float_as_int(t) - 0x4B400000;
    float f = x - (t - 12582912.0f);
    float e = fmaf(f, 0.0013333558f, 0.0096181291f);
    e = fmaf(f, e, 0.0555041087f);
    e = fmaf(f, e, 0.2402265070f);
    e = fmaf(f, e, 0.6931471806f);
    e = fmaf(f, e, 1.0f);
    return __int_as_float(__float_as_int(e) + (ei << 23));
}
#define LOG2E_F  1.4426950408889634f
#define NBIAS_F  (-11.541560327111707f)

// ---------------- fused fp16 convert of x + all weights (1 launch) ----------------
#define N4_WQ 262144
#define N4_WK 65536
#define N4_WV 65536
#define N4_WP 262144
__global__ void cvt_all(const float* __restrict__ x,  const float* __restrict__ wq,
                        const float* __restrict__ wk, const float* __restrict__ wv,
                        const float* __restrict__ wp,
                        __half* __restrict__ xo, __half* __restrict__ wqo,
                        __half* __restrict__ wko, __half* __restrict__ wvo,
                        __half* __restrict__ wpo, int n4x) {
    int i = blockIdx.x * blockDim.x + threadIdx.x;
    const float4* s; __half* d; int j;
    if (i < n4x) { s = (const float4*)x; d = xo; j = i; }
    else {
        i -= n4x;
        if (i < N4_WQ)                          { s = (const float4*)wq; d = wqo; j = i; }
        else if (i < N4_WQ + N4_WK)             { s = (const float4*)wk; d = wko; j = i - N4_WQ; }
        else if (i < N4_WQ + N4_WK + N4_WV)     { s = (const float4*)wv; d = wvo; j = i - N4_WQ - N4_WK; }
        else if (i < N4_WQ + N4_WK + N4_WV + N4_WP) { s = (const float4*)wp; d = wpo; j = i - N4_WQ - N4_WK - N4_WV; }
        else return;
    }
    float4 v = s[j];
    __half2 h0 = __floats2half2_rn(v.x, v.y);
    __half2 h1 = __floats2half2_rn(v.z, v.w);
    *reinterpret_cast<__half2*>(&d[j * 4])     = h0;
    *reinterpret_cast<__half2*>(&d[j * 4 + 2]) = h1;
}

// ================= FP16 GEMM, cp.async 3-stage, BK=64 (R13 exact) =================
__device__ __forceinline__ void gemm_core(
    const __half* __restrict__ A, const __half* __restrict__ W,
    float* __restrict__ C, int N, int K, int m0, int n0) {
    extern __shared__ __half smh[];
    __half* As = smh;                          // NSTG * 128 * LDA
    __half* Ws = smh + NSTG * BM * LDA;        // NSTG * 128 * LDA
    const int tid = threadIdx.x;
    const int warp = tid >> 5;
    const int wm = warp >> 2;
    const int wn = warp & 3;

    wmma::fragment<wmma::accumulator, 16, 16, 16, float> acc[4][2];
#pragma unroll
    for (int i = 0; i < 4; i++)
#pragma unroll
        for (int j = 0; j < 2; j++) wmma::fill_fragment(acc[i][j], 0.f);

    const __half* Ab = A + (size_t)m0 * K;
    const __half* Wb = W + (size_t)n0 * K;

#define LOAD_SLAB(it, buf)                                                      \
    {                                                                           \
        const int k0 = (it) << 6;                                               \
        __half* ad = As + (buf) * BM * LDA;                                     \
        __half* wd = Ws + (buf) * BN * LDA;                                     \
        _Pragma("unroll")                                                       \
        for (int i = 0; i < 4; i++) {                                           \
            int ch = tid + i * 256;          /* 0..1023 */                      \
            int r = ch >> 3, c8 = (ch & 7) << 3;                                \
            cp16(ad + r * LDA + c8, Ab + (size_t)r * K + k0 + c8);              \
            cp16(wd + r * LDA + c8, Wb + (size_t)r * K + k0 + c8);              \
        }                                                                       \
    }

    const int nIter = K >> 6;
    LOAD_SLAB(0, 0); CP_COMMIT();
    LOAD_SLAB(1, 1); CP_COMMIT();

    int buf = 0;
    for (int it = 0; it < nIter; ++it) {
        if (it + 1 < nIter) CP_WAIT1(); else CP_WAIT0();
        __syncthreads();
        if (it + 2 < nIter) {
            int nb = buf + 2; if (nb >= NSTG) nb -= NSTG;
            LOAD_SLAB(it + 2, nb); CP_COMMIT();
        }
        const __half* as = As + buf * BM * LDA;
        const __half* ws = Ws + buf * BN * LDA;
#pragma unroll
        for (int kk = 0; kk < BKg; kk += 16) {
            wmma::fragment<wmma::matrix_a, 16, 16, 16, __half, wmma::row_major> a[4];
            wmma::fragment<wmma::matrix_b, 16, 16, 16, __half, wmma::col_major> b[2];
#pragma unroll
            for (int i = 0; i < 4; i++)
                wmma::load_matrix_sync(a[i], &as[(wm * 64 + i * 16) * LDA + kk], LDA);
#pragma unroll
            for (int j = 0; j < 2; j++)
                wmma::load_matrix_sync(b[j], &ws[(wn * 32 + j * 16) * LDA + kk], LDA);
#pragma unroll
            for (int i = 0; i < 4; i++)
#pragma unroll
                for (int j = 0; j < 2; j++)
                    wmma::mma_sync(acc[i][j], a[i], b[j], acc[i][j]);
        }
        if (++buf == NSTG) buf = 0;
    }
#undef LOAD_SLAB
    __syncthreads();
#pragma unroll
    for (int i = 0; i < 4; i++)
#pragma unroll
        for (int j = 0; j < 2; j++)
            wmma::store_matrix_sync(&C[(size_t)(m0 + wm * 64 + i * 16) * N + n0 + wn * 32 + j * 16],
                                    acc[i][j], N, wmma::mem_row_major);
}

__global__ __launch_bounds__(256) void gemm_proj(
    const __half* __restrict__ A, const __half* __restrict__ W, float* __restrict__ C, int K) {
    gemm_core(A, W, C, Ecfg, K, blockIdx.y * BM, blockIdx.x * BN);
}

__global__ __launch_bounds__(256) void gemm_qkv(
    const __half* __restrict__ x,
    const __half* __restrict__ Wq, const __half* __restrict__ Wk, const __half* __restrict__ Wv,
    float* __restrict__ Cq, float* __restrict__ Ck, float* __restrict__ Cv, int K) {
    const int ng = blockIdx.x * BN;
    const __half* W; float* C; int N, n0;
    if (ng < 1024)      { W = Wq; C = Cq; N = 1024; n0 = ng; }
    else if (ng < 1280) { W = Wk; C = Ck; N = 256;  n0 = ng - 1024; }
    else                { W = Wv; C = Cv; N = 256;  n0 = ng - 1280; }
    gemm_core(x, W, C, N, K, blockIdx.y * BM, n0);
}

// ---------------- fused post-QKV: Q rope (y<16) / K rope + V gate (y>=16) ----------------
// grid (T/8, 20, B), 256 thr = 8 warps, one warp per token.
__global__ void qkv_post_kernel(const float* __restrict__ qraw,
                                const float* __restrict__ kraw,
                                const float* __restrict__ vraw,
                                const float* __restrict__ x,
                                const float* __restrict__ ve,
                                const float* __restrict__ cosb,
                                const float* __restrict__ sinb,
                                const float* __restrict__ Wgate,
                                __half* __restrict__ qt,
                                __half* __restrict__ kt,
                                __half* __restrict__ vt, int T) {
    const int warp = threadIdx.x >> 5, lane = threadIdx.x & 31;
    const int t = blockIdx.x * 8 + warp;
    const int yb = blockIdx.y, b = blockIdx.z;
    const size_t tok = (size_t)b * T + t;

    if (yb < Hh) {
        // Q: rope + rmsnorm, pre-scaled 1/8
        const int h = yb;
        const float* src = qraw + (tok * Hh + h) * 64;
        float x1 = src[lane], x2 = src[32 + lane];
        float c = cosb[(size_t)t * 32 + lane];
        float s = sinb[(size_t)t * 32 + lane];
        float r1 = x1 * c + x2 * s;
        float r2 = x2 * c - x1 * s;
        float ss = r1 * r1 + r2 * r2;
#pragma unroll
        for (int o = 16; o; o >>= 1) ss += __shfl_xor_sync(0xffffffffu, ss, o);
        float inv = rsqrtf(ss * (1.f / 64.f) + 1.1920929e-07f) * 0.125f;
        __half* d = qt + (((size_t)b * Hh + h) * T + t) * 64;
        d[lane] = __float2half(r1 * inv);
        d[32 + lane] = __float2half(r2 * inv);
    } else {
        const int h = yb - Hh;
        {
            const float* src = kraw + (tok * HKV + h) * 64;
            float x1 = src[lane], x2 = src[32 + lane];
            float c = cosb[(size_t)t * 32 + lane];
            float s = sinb[(size_t)t * 32 + lane];
            float r1 = x1 * c + x2 * s;
            float r2 = x2 * c - x1 * s;
            float ss = r1 * r1 + r2 * r2;
#pragma unroll
            for (int o = 16; o; o >>= 1) ss += __shfl_xor_sync(0xffffffffu, ss, o);
            float inv = rsqrtf(ss * (1.f / 64.f) + 1.1920929e-07f);
            __half* d = kt + (((size_t)b * HKV + h) * T + t) * 64;
            d[lane] = __float2half(r1 * inv);
            d[32 + lane] = __float2half(r2 * inv);
        }
        {
            float g = x[tok * Ecfg + lane] * Wgate[h * 32 + lane];
#pragma unroll
            for (int o = 16; o; o >>= 1) g += __shfl_xor_sync(0xffffffffu, g, o);
            float gate = 2.f / (1.f + __expf(-g));
            const float* vs = vraw + (tok * HKV + h) * 64;
            const float* ves = ve + (tok * HKV + h) * 64;
            __half* d = vt + (((size_t)b * HKV + h) * T + t) * 64;
            d[lane] = __float2half(vs[lane] + gate * ves[lane]);
            d[32 + lane] = __float2half(vs[32 + lane] + gate * ves[32 + lane]);
        }
    }
}

// ================ flash attention: raw mma + register softmax + per-warp chunk skip ================
// 128 thr = 4 warps; warp owns rows [32w, 32w+32) of a 128-row Q tile.
// Inner t-chunk loop has NO block syncs -> each warp may skip chunks that are
// entirely masked for its rows (fully-future or fully-outside-window).
__global__ __launch_bounds__(128) void attn_mma(
    const __half* __restrict__ q, const __half* __restrict__ k,
    const __half* __restrict__ v, __half* __restrict__ out,
    const int* __restrict__ wptr, int T) {
    extern __shared__ __half smh[];
    __half* Ks = smh;                  // 2 * 64 * LDK
    __half* Vs = smh + 2 * 64 * LDK;   // 2 * 64 * LDK
    const uint32_t ks0 = smem_u32(Ks);
    const uint32_t vs0 = smem_u32(Vs);

    const int qtile = blockIdx.x, h = blockIdx.y, b = blockIdx.z;
    const int W = wptr[0];
    const int tid = threadIdx.x;
    const int warp = tid >> 5, lane = tid & 31;
    const int qbase = qtile * 128;
    const int rq = lane >> 2;
    const int qc = (lane & 3) << 1;
    const int rowMin = qbase + warp * 32;        // warp's first query row
    const int rowMax = rowMin + 31;              // warp's last query row

    const int krow = ((lane >> 4) << 3) + (lane & 7);
    const int kcol = ((lane >> 3) & 1) << 3;
    const int vrow = (((lane >> 3) & 1) << 3) + (lane & 7);
    const int vcol = (lane >> 4) << 3;

    uint32_t qa[2][4][4];
#pragma unroll
    for (int i = 0; i < 2; i++) {
        const __half* q0 = q + ((size_t)(b * Hh + h) * T + qbase + warp * 32 + i * 16 + rq) * Dd;
        const __half* q8 = q0 + 8 * Dd;
#pragma unroll
        for (int t = 0; t < 4; t++) {
            qa[i][t][0] = *reinterpret_cast<const uint32_t*>(q0 + t * 16 + qc);
            qa[i][t][1] = *reinterpret_cast<const uint32_t*>(q8 + t * 16 + qc);
            qa[i][t][2] = *reinterpret_cast<const uint32_t*>(q0 + t * 16 + 8 + qc);
            qa[i][t][3] = *reinterpret_cast<const uint32_t*>(q8 + t * 16 + 8 + qc);
        }
    }

    float o[2][8][4];
#pragma unroll
    for (int i = 0; i < 2; i++)
#pragma unroll
        for (int j = 0; j < 8; j++)
#pragma unroll
            for (int c = 0; c < 4; c++) o[i][j][c] = 0.f;
    float lsum[2][2] = {{0.f, 0.f}, {0.f, 0.f}};

    const int hkv = h >> 2;
    const __half* kb = k + (size_t)(b * HKV + hkv) * T * Dd;
    const __half* vb = v + (size_t)(b * HKV + hkv) * T * Dd;
    int kmin = qbase - W; if (kmin < 0) kmin = 0;
    const int t0 = kmin >> 6;
    const int ktend = 2 * qtile + 1;

#define LOAD_KV(kt, buf)                                                        \
    {                                                                           \
        const __half* kp = kb + (size_t)(kt) * 64 * Dd;                         \
        const __half* vp = vb + (size_t)(kt) * 64 * Dd;                         \
        __half* kd = Ks + (buf) * 64 * LDK;                                     \
        __half* vd = Vs + (buf) * 64 * LDK;                                     \
        _Pragma("unroll")                                                       \
        for (int i = 0; i < 4; i++) {                                           \
            int ch = tid + i * 128;                                             \
            int r = ch >> 3, c8 = (ch & 7) << 3;                                \
            cp16(kd + r * LDK + c8, kp + r * 64 + c8);                          \
            cp16(vd + r * LDK + c8, vp + r * 64 + c8);                          \
        }                                                                       \
    }

    LOAD_KV(t0, 0); CP_COMMIT();

    for (int kt = t0; kt <= ktend; ++kt) {
        const int buf = (kt - t0) & 1;
        if (kt < ktend) { LOAD_KV(kt + 1, buf ^ 1); CP_COMMIT(); CP_WAIT1(); }
        else CP_WAIT0();
        __syncthreads();
        const uint32_t ksb = ks0 + buf * 64 * LDK * 2;
        const uint32_t vsb = vs0 + buf * 64 * LDK * 2;

#pragma unroll
        for (int t = 0; t < 4; t++) {
            const int chunk0 = (kt << 6) + t * 16;        // first key col of chunk
            // per-warp skip: entirely future, or entirely before the window
            if (chunk0 > rowMax) continue;                 // all cols > every row
            if (chunk0 + 15 < rowMin - W) continue;        // all cols < every row - W
            float s[2][2][4];
#pragma unroll
            for (int i = 0; i < 2; i++)
#pragma unroll
                for (int jj = 0; jj < 2; jj++)
#pragma unroll
                    for (int c = 0; c < 4; c++) s[i][jj][c] = 0.f;
#pragma unroll
            for (int kd = 0; kd < 4; kd++) {
                uint32_t kbf[4];
                ldm4(kbf, ksb + (uint32_t)(((t * 16 + krow) * LDK + kd * 16 + kcol) * 2));
                mma16816(s[0][0], qa[0][kd], kbf[0], kbf[1]);
                mma16816(s[0][1], qa[0][kd], kbf[2], kbf[3]);
                mma16816(s[1][0], qa[1][kd], kbf[0], kbf[1]);
                mma16816(s[1][1], qa[1][kd], kbf[2], kbf[3]);
            }
            uint32_t pa[2][4];
#pragma unroll
            for (int i = 0; i < 2; i++) {
                const int row0 = qbase + warp * 32 + i * 16 + rq;
#pragma unroll
                for (int jj = 0; jj < 2; jj++) {
                    const int colb = chunk0 + jj * 8 + qc;
#pragma unroll
                    for (int c = 0; c < 4; c++) {
                        const int row = row0 + ((c >> 1) << 3);
                        const int col = colb + (c & 1);
                        float pv = 0.f;
                        if (col <= row && col >= row - W) {
                            pv = fast_exp2(fmaf(s[i][jj][c], LOG2E_F, NBIAS_F));
                            lsum[i][c >> 1] += pv;
                        }
                        s[i][jj][c] = pv;
                    }
                    __half2 lo = __floats2half2_rn(s[i][jj][0], s[i][jj][1]);
                    __half2 hi = __floats2half2_rn(s[i][jj][2], s[i][jj][3]);
                    pa[i][jj * 2 + 0] = *reinterpret_cast<uint32_t*>(&lo);
                    pa[i][jj * 2 + 1] = *reinterpret_cast<uint32_t*>(&hi);
                }
            }
#pragma unroll
            for (int jdp = 0; jdp < 4; jdp++) {
                uint32_t vbf[4];
                ldm4t(vbf, vsb + (uint32_t)(((t * 16 + vrow) * LDK + jdp * 16 + vcol) * 2));
                mma16816(o[0][jdp * 2 + 0], pa[0], vbf[0], vbf[1]);
                mma16816(o[0][jdp * 2 + 1], pa[0], vbf[2], vbf[3]);
                mma16816(o[1][jdp * 2 + 0], pa[1], vbf[0], vbf[1]);
                mma16816(o[1][jdp * 2 + 1], pa[1], vbf[2], vbf[3]);
            }
        }
        __syncthreads();
    }
#undef LOAD_KV

#pragma unroll
    for (int i = 0; i < 2; i++) {
#pragma unroll
        for (int rh = 0; rh < 2; rh++) {
            float l = lsum[i][rh];
            l += __shfl_xor_sync(0xffffffffu, l, 1);
            l += __shfl_xor_sync(0xffffffffu, l, 2);
            const float inv = 1.f / l;
            const int qrow = qbase + warp * 32 + i * 16 + rq + rh * 8;
            __half* op = out + ((size_t)(b * T + qrow) * Hh + h) * Dd + qc;
#pragma unroll
            for (int jd = 0; jd < 8; jd++) {
                __half2 hv = __floats2half2_rn(o[i][jd][rh * 2] * inv,
                                               o[i][jd][rh * 2 + 1] * inv);
                *reinterpret_cast<__half2*>(op + jd * 8) = hv;
            }
        }
    }
}

// ---------------- launch ----------------
extern "C" void kernel_launch(void* const* d_in, const int* in_sizes, int n_in,
                              void* d_out, int out_size) {
    const float* x     = (const float*)d_in[0];
    const float* ve    = (const float*)d_in[1];
    const float* cosb  = (const float*)d_in[2];
    const float* sinb  = (const float*)d_in[3];
    const float* Wq    = (const float*)d_in[4];
    const float* Wk    = (const float*)d_in[5];
    const float* Wv    = (const float*)d_in[6];
    const float* Wproj = (const float*)d_in[7];
    const float* Wgate = (const float*)d_in[8];
    const int*   wsz   = (const int*)d_in[9];

    int T = in_sizes[2] / 32;
    int B = in_sizes[0] / (T * Ecfg);
    int M = B * T;

    float *qraw, *kraw, *vraw;
    __half *qt, *kt, *vt, *y, *xh, *wqh, *wkh, *wvh, *wph;
    cudaGetSymbolAddress((void**)&qraw, g_qraw);
    cudaGetSymbolAddress((void**)&kraw, g_kraw);
    cudaGetSymbolAddress((void**)&vraw, g_vraw);
    cudaGetSymbolAddress((void**)&qt,   g_qt);
    cudaGetSymbolAddress((void**)&kt,   g_kt);
    cudaGetSymbolAddress((void**)&vt,   g_vt);
    cudaGetSymbolAddress((void**)&y,    g_y);
    cudaGetSymbolAddress((void**)&xh,   g_xh);
    cudaGetSymbolAddress((void**)&wqh,  g_wqh);
    cudaGetSymbolAddress((void**)&wkh,  g_wkh);
    cudaGetSymbolAddress((void**)&wvh,  g_wvh);
    cudaGetSymbolAddress((void**)&wph,  g_wph);

    const int gemm_smem = NSTG * (BM + BN) * LDA * 2;   // 110592
    const int attn_smem = 4 * 64 * LDK * 2;             // 36864
    cudaFuncSetAttribute(gemm_qkv,  cudaFuncAttributeMaxDynamicSharedMemorySize, gemm_smem);
    cudaFuncSetAttribute(gemm_proj, cudaFuncAttributeMaxDynamicSharedMemorySize, gemm_smem);
    cudaFuncSetAttribute(attn_mma,  cudaFuncAttributeMaxDynamicSharedMemorySize, attn_smem);

    {
        int n4x = M * Ecfg / 4;
        int total = n4x + N4_WQ + N4_WK + N4_WV + N4_WP;
        cvt_all<<<(total + 255) / 256, 256>>>(x, Wq, Wk, Wv, Wproj,
                                              xh, wqh, wkh, wvh, wph, n4x);
    }

    gemm_qkv<<<dim3(1536 / BN, M / BM), 256, gemm_smem>>>(xh, wqh, wkh, wvh, qraw, kraw, vraw, Ecfg);

    qkv_post_kernel<<<dim3(T / 8, Hh + HKV, B), 256>>>(qraw, kraw, vraw, x, ve,
                                                       cosb, sinb, Wgate, qt, kt, vt, T);

    attn_mma<<<dim3(T / 128, Hh, B), 128, attn_smem>>>(qt, kt, vt, y, wsz, T);

    gemm_proj<<<dim3(Ecfg / BN, M / BM), 256, gemm_smem>>>(y, wph, (float*)d_out, Ecfg);
}

// round 16
// speedup vs baseline: 1.3020x; 1.1809x over previous
#include <cuda_runtime.h>
#include <cuda_fp16.h>
#include <mma.h>
#include <cstdint>

using namespace nvcuda;

#define Ecfg 1024
#define Hh   16
#define HKV  4
#define Dd   64

#define BM  128
#define BN  128
#define BKg 64
#define LDA 72    // halves (64 + 8 pad)
#define LDK 72    // halves
#define NSTG 3    // cp.async pipeline stages (GEMM)

// ---------------- scratch (device globals) ----------------
__device__ float  g_qraw[2 * 2048 * 1024];
__device__ float  g_kraw[2 * 2048 * 256];
__device__ float  g_vraw[2 * 2048 * 256];
__device__ __half g_qt [2 * 16 * 2048 * 64];
__device__ __half g_kt [2 * 4  * 2048 * 64];
__device__ __half g_vt [2 * 4  * 2048 * 64];
__device__ __half g_y  [2 * 2048 * 1024];
__device__ __half g_xh [2 * 2048 * 1024];
__device__ __half g_wqh[1024 * 1024];
__device__ __half g_wkh[256 * 1024];
__device__ __half g_wvh[256 * 1024];
__device__ __half g_wph[1024 * 1024];

// ---------------- cp.async helpers ----------------
__device__ __forceinline__ void cp16(void* smem_dst, const void* gsrc) {
    uint32_t s = (uint32_t)__cvta_generic_to_shared(smem_dst);
    asm volatile("cp.async.cg.shared.global [%0], [%1], 16;\n" :: "r"(s), "l"(gsrc));
}
#define CP_COMMIT() asm volatile("cp.async.commit_group;\n" ::: "memory")
#define CP_WAIT1()  asm volatile("cp.async.wait_group 1;\n" ::: "memory")
#define CP_WAIT0()  asm volatile("cp.async.wait_group 0;\n" ::: "memory")

__device__ __forceinline__ uint32_t smem_u32(const void* p) {
    return (uint32_t)__cvta_generic_to_shared(p);
}

// ---------------- mma / ldmatrix primitives ----------------
__device__ __forceinline__ void mma16816(float d[4], const uint32_t a[4],
                                         uint32_t b0, uint32_t b1) {
    asm volatile(
        "mma.sync.aligned.m16n8k16.row.col.f32.f16.f16.f32 "
        "{%0,%1,%2,%3}, {%4,%5,%6,%7}, {%8,%9}, {%0,%1,%2,%3};"
        : "+f"(d[0]), "+f"(d[1]), "+f"(d[2]), "+f"(d[3])
        : "r"(a[0]), "r"(a[1]), "r"(a[2]), "r"(a[3]), "r"(b0), "r"(b1));
}
__device__ __forceinline__ void ldm4(uint32_t r[4], uint32_t addr) {
    asm volatile("ldmatrix.sync.aligned.m8n8.x4.shared.b16 {%0,%1,%2,%3}, [%4];"
                 : "=r"(r[0]), "=r"(r[1]), "=r"(r[2]), "=r"(r[3]) : "r"(addr));
}
__device__ __forceinline__ void ldm4t(uint32_t r[4], uint32_t addr) {
    asm volatile("ldmatrix.sync.aligned.m8n8.x4.trans.shared.b16 {%0,%1,%2,%3}, [%4];"
                 : "=r"(r[0]), "=r"(r[1]), "=r"(r[2]), "=r"(r[3]) : "r"(addr));
}

// ---------------- fast exp2 (no MUFU) ----------------
__device__ __forceinline__ float fast_exp2(float x) {
    float t = x + 12582912.0f;
    int   ei = __float_as_int(t) - 0x4B400000;
    float f = x - (t - 12582912.0f);
    float e = fmaf(f, 0.0013333558f, 0.0096181291f);
    e = fmaf(f, e, 0.0555041087f);
    e = fmaf(f, e, 0.2402265070f);
    e = fmaf(f, e, 0.6931471806f);
    e = fmaf(f, e, 1.0f);
    return __int_as_float(__float_as_int(e) + (ei << 23));
}
#define LOG2E_F  1.4426950408889634f
#define NBIAS_F  (-11.541560327111707f)

// ---------------- fused fp16 convert of x + all weights (1 launch) ----------------
#define N4_WQ 262144
#define N4_WK 65536
#define N4_WV 65536
#define N4_WP 262144
__global__ void cvt_all(const float* __restrict__ x,  const float* __restrict__ wq,
                        const float* __restrict__ wk, const float* __restrict__ wv,
                        const float* __restrict__ wp,
                        __half* __restrict__ xo, __half* __restrict__ wqo,
                        __half* __restrict__ wko, __half* __restrict__ wvo,
                        __half* __restrict__ wpo, int n4x) {
    int i = blockIdx.x * blockDim.x + threadIdx.x;
    const float4* s; __half* d; int j;
    if (i < n4x) { s = (const float4*)x; d = xo; j = i; }
    else {
        i -= n4x;
        if (i < N4_WQ)                          { s = (const float4*)wq; d = wqo; j = i; }
        else if (i < N4_WQ + N4_WK)             { s = (const float4*)wk; d = wko; j = i - N4_WQ; }
        else if (i < N4_WQ + N4_WK + N4_WV)     { s = (const float4*)wv; d = wvo; j = i - N4_WQ - N4_WK; }
        else if (i < N4_WQ + N4_WK + N4_WV + N4_WP) { s = (const float4*)wp; d = wpo; j = i - N4_WQ - N4_WK - N4_WV; }
        else return;
    }
    float4 v = s[j];
    __half2 h0 = __floats2half2_rn(v.x, v.y);
    __half2 h1 = __floats2half2_rn(v.z, v.w);
    *reinterpret_cast<__half2*>(&d[j * 4])     = h0;
    *reinterpret_cast<__half2*>(&d[j * 4 + 2]) = h1;
}

// ================= FP16 GEMM, cp.async 3-stage, BK=64 (R13 exact) =================
__device__ __forceinline__ void gemm_core(
    const __half* __restrict__ A, const __half* __restrict__ W,
    float* __restrict__ C, int N, int K, int m0, int n0) {
    extern __shared__ __half smh[];
    __half* As = smh;                          // NSTG * 128 * LDA
    __half* Ws = smh + NSTG * BM * LDA;        // NSTG * 128 * LDA
    const int tid = threadIdx.x;
    const int warp = tid >> 5;
    const int wm = warp >> 2;
    const int wn = warp & 3;

    wmma::fragment<wmma::accumulator, 16, 16, 16, float> acc[4][2];
#pragma unroll
    for (int i = 0; i < 4; i++)
#pragma unroll
        for (int j = 0; j < 2; j++) wmma::fill_fragment(acc[i][j], 0.f);

    const __half* Ab = A + (size_t)m0 * K;
    const __half* Wb = W + (size_t)n0 * K;

#define LOAD_SLAB(it, buf)                                                      \
    {                                                                           \
        const int k0 = (it) << 6;                                               \
        __half* ad = As + (buf) * BM * LDA;                                     \
        __half* wd = Ws + (buf) * BN * LDA;                                     \
        _Pragma("unroll")                                                       \
        for (int i = 0; i < 4; i++) {                                           \
            int ch = tid + i * 256;          /* 0..1023 */                      \
            int r = ch >> 3, c8 = (ch & 7) << 3;                                \
            cp16(ad + r * LDA + c8, Ab + (size_t)r * K + k0 + c8);              \
            cp16(wd + r * LDA + c8, Wb + (size_t)r * K + k0 + c8);              \
        }                                                                       \
    }

    const int nIter = K >> 6;
    LOAD_SLAB(0, 0); CP_COMMIT();
    LOAD_SLAB(1, 1); CP_COMMIT();

    int buf = 0;
    for (int it = 0; it < nIter; ++it) {
        if (it + 1 < nIter) CP_WAIT1(); else CP_WAIT0();
        __syncthreads();
        if (it + 2 < nIter) {
            int nb = buf + 2; if (nb >= NSTG) nb -= NSTG;
            LOAD_SLAB(it + 2, nb); CP_COMMIT();
        }
        const __half* as = As + buf * BM * LDA;
        const __half* ws = Ws + buf * BN * LDA;
#pragma unroll
        for (int kk = 0; kk < BKg; kk += 16) {
            wmma::fragment<wmma::matrix_a, 16, 16, 16, __half, wmma::row_major> a[4];
            wmma::fragment<wmma::matrix_b, 16, 16, 16, __half, wmma::col_major> b[2];
#pragma unroll
            for (int i = 0; i < 4; i++)
                wmma::load_matrix_sync(a[i], &as[(wm * 64 + i * 16) * LDA + kk], LDA);
#pragma unroll
            for (int j = 0; j < 2; j++)
                wmma::load_matrix_sync(b[j], &ws[(wn * 32 + j * 16) * LDA + kk], LDA);
#pragma unroll
            for (int i = 0; i < 4; i++)
#pragma unroll
                for (int j = 0; j < 2; j++)
                    wmma::mma_sync(acc[i][j], a[i], b[j], acc[i][j]);
        }
        if (++buf == NSTG) buf = 0;
    }
#undef LOAD_SLAB
    __syncthreads();
#pragma unroll
    for (int i = 0; i < 4; i++)
#pragma unroll
        for (int j = 0; j < 2; j++)
            wmma::store_matrix_sync(&C[(size_t)(m0 + wm * 64 + i * 16) * N + n0 + wn * 32 + j * 16],
                                    acc[i][j], N, wmma::mem_row_major);
}

__global__ __launch_bounds__(256) void gemm_proj(
    const __half* __restrict__ A, const __half* __restrict__ W, float* __restrict__ C, int K) {
    gemm_core(A, W, C, Ecfg, K, blockIdx.y * BM, blockIdx.x * BN);
}

__global__ __launch_bounds__(256) void gemm_qkv(
    const __half* __restrict__ x,
    const __half* __restrict__ Wq, const __half* __restrict__ Wk, const __half* __restrict__ Wv,
    float* __restrict__ Cq, float* __restrict__ Ck, float* __restrict__ Cv, int K) {
    const int ng = blockIdx.x * BN;
    const __half* W; float* C; int N, n0;
    if (ng < 1024)      { W = Wq; C = Cq; N = 1024; n0 = ng; }
    else if (ng < 1280) { W = Wk; C = Ck; N = 256;  n0 = ng - 1024; }
    else                { W = Wv; C = Cv; N = 256;  n0 = ng - 1280; }
    gemm_core(x, W, C, N, K, blockIdx.y * BM, n0);
}

// ---------------- fused post-QKV: Q rope (y<16) / K rope + V gate (y>=16) ----------------
__global__ void qkv_post_kernel(const float* __restrict__ qraw,
                                const float* __restrict__ kraw,
                                const float* __restrict__ vraw,
                                const float* __restrict__ x,
                                const float* __restrict__ ve,
                                const float* __restrict__ cosb,
                                const float* __restrict__ sinb,
                                const float* __restrict__ Wgate,
                                __half* __restrict__ qt,
                                __half* __restrict__ kt,
                                __half* __restrict__ vt, int T) {
    const int warp = threadIdx.x >> 5, lane = threadIdx.x & 31;
    const int t = blockIdx.x * 8 + warp;
    const int yb = blockIdx.y, b = blockIdx.z;
    const size_t tok = (size_t)b * T + t;

    if (yb < Hh) {
        const int h = yb;
        const float* src = qraw + (tok * Hh + h) * 64;
        float x1 = src[lane], x2 = src[32 + lane];
        float c = cosb[(size_t)t * 32 + lane];
        float s = sinb[(size_t)t * 32 + lane];
        float r1 = x1 * c + x2 * s;
        float r2 = x2 * c - x1 * s;
        float ss = r1 * r1 + r2 * r2;
#pragma unroll
        for (int o = 16; o; o >>= 1) ss += __shfl_xor_sync(0xffffffffu, ss, o);
        float inv = rsqrtf(ss * (1.f / 64.f) + 1.1920929e-07f) * 0.125f;
        __half* d = qt + (((size_t)b * Hh + h) * T + t) * 64;
        d[lane] = __float2half(r1 * inv);
        d[32 + lane] = __float2half(r2 * inv);
    } else {
        const int h = yb - Hh;
        {
            const float* src = kraw + (tok * HKV + h) * 64;
            float x1 = src[lane], x2 = src[32 + lane];
            float c = cosb[(size_t)t * 32 + lane];
            float s = sinb[(size_t)t * 32 + lane];
            float r1 = x1 * c + x2 * s;
            float r2 = x2 * c - x1 * s;
            float ss = r1 * r1 + r2 * r2;
#pragma unroll
            for (int o = 16; o; o >>= 1) ss += __shfl_xor_sync(0xffffffffu, ss, o);
            float inv = rsqrtf(ss * (1.f / 64.f) + 1.1920929e-07f);
            __half* d = kt + (((size_t)b * HKV + h) * T + t) * 64;
            d[lane] = __float2half(r1 * inv);
            d[32 + lane] = __float2half(r2 * inv);
        }
        {
            float g = x[tok * Ecfg + lane] * Wgate[h * 32 + lane];
#pragma unroll
            for (int o = 16; o; o >>= 1) g += __shfl_xor_sync(0xffffffffu, g, o);
            float gate = 2.f / (1.f + __expf(-g));
            const float* vs = vraw + (tok * HKV + h) * 64;
            const float* ves = ve + (tok * HKV + h) * 64;
            __half* d = vt + (((size_t)b * HKV + h) * T + t) * 64;
            d[lane] = __float2half(vs[lane] + gate * ves[lane]);
            d[32 + lane] = __float2half(vs[32 + lane] + gate * ves[32 + lane]);
        }
    }
}

// ================ flash attention: raw mma + register softmax + uniform-mask fast path ================
// 128 thr = 4 warps; warp owns rows [32w, 32w+32). Per-warp chunk classification:
//   - fully masked -> skip;  - fully valid -> exp with NO per-element compares;
//   - boundary     -> masked path.
__global__ __launch_bounds__(128) void attn_mma(
    const __half* __restrict__ q, const __half* __restrict__ k,
    const __half* __restrict__ v, __half* __restrict__ out,
    const int* __restrict__ wptr, int T) {
    extern __shared__ __half smh[];
    __half* Ks = smh;                  // 2 * 64 * LDK
    __half* Vs = smh + 2 * 64 * LDK;   // 2 * 64 * LDK
    const uint32_t ks0 = smem_u32(Ks);
    const uint32_t vs0 = smem_u32(Vs);

    const int qtile = blockIdx.x, h = blockIdx.y, b = blockIdx.z;
    const int W = wptr[0];
    const int tid = threadIdx.x;
    const int warp = tid >> 5, lane = tid & 31;
    const int qbase = qtile * 128;
    const int rq = lane >> 2;
    const int qc = (lane & 3) << 1;
    const int rowMin = qbase + warp * 32;
    const int rowMax = rowMin + 31;

    const int krow = ((lane >> 4) << 3) + (lane & 7);
    const int kcol = ((lane >> 3) & 1) << 3;
    const int vrow = (((lane >> 3) & 1) << 3) + (lane & 7);
    const int vcol = (lane >> 4) << 3;

    uint32_t qa[2][4][4];
#pragma unroll
    for (int i = 0; i < 2; i++) {
        const __half* q0 = q + ((size_t)(b * Hh + h) * T + qbase + warp * 32 + i * 16 + rq) * Dd;
        const __half* q8 = q0 + 8 * Dd;
#pragma unroll
        for (int t = 0; t < 4; t++) {
            qa[i][t][0] = *reinterpret_cast<const uint32_t*>(q0 + t * 16 + qc);
            qa[i][t][1] = *reinterpret_cast<const uint32_t*>(q8 + t * 16 + qc);
            qa[i][t][2] = *reinterpret_cast<const uint32_t*>(q0 + t * 16 + 8 + qc);
            qa[i][t][3] = *reinterpret_cast<const uint32_t*>(q8 + t * 16 + 8 + qc);
        }
    }

    float o[2][8][4];
#pragma unroll
    for (int i = 0; i < 2; i++)
#pragma unroll
        for (int j = 0; j < 8; j++)
#pragma unroll
            for (int c = 0; c < 4; c++) o[i][j][c] = 0.f;
    float lsum[2][2] = {{0.f, 0.f}, {0.f, 0.f}};

    const int hkv = h >> 2;
    const __half* kb = k + (size_t)(b * HKV + hkv) * T * Dd;
    const __half* vb = v + (size_t)(b * HKV + hkv) * T * Dd;
    int kmin = qbase - W; if (kmin < 0) kmin = 0;
    const int t0 = kmin >> 6;
    const int ktend = 2 * qtile + 1;

#define LOAD_KV(kt, buf)                                                        \
    {                                                                           \
        const __half* kp = kb + (size_t)(kt) * 64 * Dd;                         \
        const __half* vp = vb + (size_t)(kt) * 64 * Dd;                         \
        __half* kd = Ks + (buf) * 64 * LDK;                                     \
        __half* vd = Vs + (buf) * 64 * LDK;                                     \
        _Pragma("unroll")                                                       \
        for (int i = 0; i < 4; i++) {                                           \
            int ch = tid + i * 128;                                             \
            int r = ch >> 3, c8 = (ch & 7) << 3;                                \
            cp16(kd + r * LDK + c8, kp + r * 64 + c8);                          \
            cp16(vd + r * LDK + c8, vp + r * 64 + c8);                          \
        }                                                                       \
    }

    LOAD_KV(t0, 0); CP_COMMIT();

    for (int kt = t0; kt <= ktend; ++kt) {
        const int buf = (kt - t0) & 1;
        if (kt < ktend) { LOAD_KV(kt + 1, buf ^ 1); CP_COMMIT(); CP_WAIT1(); }
        else CP_WAIT0();
        __syncthreads();
        const uint32_t ksb = ks0 + buf * 64 * LDK * 2;
        const uint32_t vsb = vs0 + buf * 64 * LDK * 2;

#pragma unroll
        for (int t = 0; t < 4; t++) {
            const int chunk0 = (kt << 6) + t * 16;
            if (chunk0 > rowMax) continue;                 // fully future
            if (chunk0 + 15 < rowMin - W) continue;        // fully pre-window
            const bool fullv = (chunk0 + 15 <= rowMin) && (chunk0 >= rowMax - W);

            float s[2][2][4];
#pragma unroll
            for (int i = 0; i < 2; i++)
#pragma unroll
                for (int jj = 0; jj < 2; jj++)
#pragma unroll
                    for (int c = 0; c < 4; c++) s[i][jj][c] = 0.f;
#pragma unroll
            for (int kd = 0; kd < 4; kd++) {
                uint32_t kbf[4];
                ldm4(kbf, ksb + (uint32_t)(((t * 16 + krow) * LDK + kd * 16 + kcol) * 2));
                mma16816(s[0][0], qa[0][kd], kbf[0], kbf[1]);
                mma16816(s[0][1], qa[0][kd], kbf[2], kbf[3]);
                mma16816(s[1][0], qa[1][kd], kbf[0], kbf[1]);
                mma16816(s[1][1], qa[1][kd], kbf[2], kbf[3]);
            }
            uint32_t pa[2][4];
            if (fullv) {
                // no per-element masking: straight exp + sum
#pragma unroll
                for (int i = 0; i < 2; i++)
#pragma unroll
                    for (int jj = 0; jj < 2; jj++) {
#pragma unroll
                        for (int c = 0; c < 4; c++) {
                            float pv = fast_exp2(fmaf(s[i][jj][c], LOG2E_F, NBIAS_F));
                            lsum[i][c >> 1] += pv;
                            s[i][jj][c] = pv;
                        }
                        __half2 lo = __floats2half2_rn(s[i][jj][0], s[i][jj][1]);
                        __half2 hi = __floats2half2_rn(s[i][jj][2], s[i][jj][3]);
                        pa[i][jj * 2 + 0] = *reinterpret_cast<uint32_t*>(&lo);
                        pa[i][jj * 2 + 1] = *reinterpret_cast<uint32_t*>(&hi);
                    }
            } else {
#pragma unroll
                for (int i = 0; i < 2; i++) {
                    const int row0 = qbase + warp * 32 + i * 16 + rq;
#pragma unroll
                    for (int jj = 0; jj < 2; jj++) {
                        const int colb = chunk0 + jj * 8 + qc;
#pragma unroll
                        for (int c = 0; c < 4; c++) {
                            const int row = row0 + ((c >> 1) << 3);
                            const int col = colb + (c & 1);
                            float pv = 0.f;
                            if (col <= row && col >= row - W) {
                                pv = fast_exp2(fmaf(s[i][jj][c], LOG2E_F, NBIAS_F));
                                lsum[i][c >> 1] += pv;
                            }
                            s[i][jj][c] = pv;
                        }
                        __half2 lo = __floats2half2_rn(s[i][jj][0], s[i][jj][1]);
                        __half2 hi = __floats2half2_rn(s[i][jj][2], s[i][jj][3]);
                        pa[i][jj * 2 + 0] = *reinterpret_cast<uint32_t*>(&lo);
                        pa[i][jj * 2 + 1] = *reinterpret_cast<uint32_t*>(&hi);
                    }
                }
            }
#pragma unroll
            for (int jdp = 0; jdp < 4; jdp++) {
                uint32_t vbf[4];
                ldm4t(vbf, vsb + (uint32_t)(((t * 16 + vrow) * LDK + jdp * 16 + vcol) * 2));
                mma16816(o[0][jdp * 2 + 0], pa[0], vbf[0], vbf[1]);
                mma16816(o[0][jdp * 2 + 1], pa[0], vbf[2], vbf[3]);
                mma16816(o[1][jdp * 2 + 0], pa[1], vbf[0], vbf[1]);
                mma16816(o[1][jdp * 2 + 1], pa[1], vbf[2], vbf[3]);
            }
        }
        __syncthreads();
    }
#undef LOAD_KV

#pragma unroll
    for (int i = 0; i < 2; i++) {
#pragma unroll
        for (int rh = 0; rh < 2; rh++) {
            float l = lsum[i][rh];
            l += __shfl_xor_sync(0xffffffffu, l, 1);
            l += __shfl_xor_sync(0xffffffffu, l, 2);
            const float inv = 1.f / l;
            const int qrow = qbase + warp * 32 + i * 16 + rq + rh * 8;
            __half* op = out + ((size_t)(b * T + qrow) * Hh + h) * Dd + qc;
#pragma unroll
            for (int jd = 0; jd < 8; jd++) {
                __half2 hv = __floats2half2_rn(o[i][jd][rh * 2] * inv,
                                               o[i][jd][rh * 2 + 1] * inv);
                *reinterpret_cast<__half2*>(op + jd * 8) = hv;
            }
        }
    }
}

// ---------------- launch ----------------
extern "C" void kernel_launch(void* const* d_in, const int* in_sizes, int n_in,
                              void* d_out, int out_size) {
    const float* x     = (const float*)d_in[0];
    const float* ve    = (const float*)d_in[1];
    const float* cosb  = (const float*)d_in[2];
    const float* sinb  = (const float*)d_in[3];
    const float* Wq    = (const float*)d_in[4];
    const float* Wk    = (const float*)d_in[5];
    const float* Wv    = (const float*)d_in[6];
    const float* Wproj = (const float*)d_in[7];
    const float* Wgate = (const float*)d_in[8];
    const int*   wsz   = (const int*)d_in[9];

    int T = in_sizes[2] / 32;
    int B = in_sizes[0] / (T * Ecfg);
    int M = B * T;

    float *qraw, *kraw, *vraw;
    __half *qt, *kt, *vt, *y, *xh, *wqh, *wkh, *wvh, *wph;
    cudaGetSymbolAddress((void**)&qraw, g_qraw);
    cudaGetSymbolAddress((void**)&kraw, g_kraw);
    cudaGetSymbolAddress((void**)&vraw, g_vraw);
    cudaGetSymbolAddress((void**)&qt,   g_qt);
    cudaGetSymbolAddress((void**)&kt,   g_kt);
    cudaGetSymbolAddress((void**)&vt,   g_vt);
    cudaGetSymbolAddress((void**)&y,    g_y);
    cudaGetSymbolAddress((void**)&xh,   g_xh);
    cudaGetSymbolAddress((void**)&wqh,  g_wqh);
    cudaGetSymbolAddress((void**)&wkh,  g_wkh);
    cudaGetSymbolAddress((void**)&wvh,  g_wvh);
    cudaGetSymbolAddress((void**)&wph,  g_wph);

    const int gemm_smem = NSTG * (BM + BN) * LDA * 2;   // 110592
    const int attn_smem = 4 * 64 * LDK * 2;             // 36864
    cudaFuncSetAttribute(gemm_qkv,  cudaFuncAttributeMaxDynamicSharedMemorySize, gemm_smem);
    cudaFuncSetAttribute(gemm_proj, cudaFuncAttributeMaxDynamicSharedMemorySize, gemm_smem);
    cudaFuncSetAttribute(attn_mma,  cudaFuncAttributeMaxDynamicSharedMemorySize, attn_smem);

    {
        int n4x = M * Ecfg / 4;
        int total = n4x + N4_WQ + N4_WK + N4_WV + N4_WP;
        cvt_all<<<(total + 255) / 256, 256>>>(x, Wq, Wk, Wv, Wproj,
                                              xh, wqh, wkh, wvh, wph, n4x);
    }

    gemm_qkv<<<dim3(1536 / BN, M / BM), 256, gemm_smem>>>(xh, wqh, wkh, wvh, qraw, kraw, vraw, Ecfg);

    qkv_post_kernel<<<dim3(T / 8, Hh + HKV, B), 256>>>(qraw, kraw, vraw, x, ve,
                                                       cosb, sinb, Wgate, qt, kt, vt, T);

    attn_mma<<<dim3(T / 128, Hh, B), 128, attn_smem>>>(qt, kt, vt, y, wsz, T);

    gemm_proj<<<dim3(Ecfg / BN, M / BM), 256, gemm_smem>>>(y, wph, (float*)d_out, Ecfg);
}

// round 17
// speedup vs baseline: 1.3788x; 1.0590x over previous
#include <cuda_runtime.h>
#include <cuda_fp16.h>
#include <mma.h>
#include <cstdint>

using namespace nvcuda;

#define Ecfg 1024
#define Hh   16
#define HKV  4
#define Dd   64

#define BM  128
#define BN  128
#define BKg 64
#define LDA 72    // halves (64 + 8 pad)
#define LDK 72    // halves
#define NSTG 3    // cp.async pipeline stages (GEMM)

// ---------------- scratch (device globals) ----------------
__device__ float  g_qraw[2 * 2048 * 1024];
__device__ float  g_kraw[2 * 2048 * 256];
__device__ float  g_vraw[2 * 2048 * 256];
__device__ __half g_qt [2 * 16 * 2048 * 64];
__device__ __half g_kt [2 * 4  * 2048 * 64];
__device__ __half g_vt [2 * 4  * 2048 * 64];
__device__ __half g_y  [2 * 2048 * 1024];
__device__ __half g_xh [2 * 2048 * 1024];
__device__ __half g_wqh[1024 * 1024];
__device__ __half g_wkh[256 * 1024];
__device__ __half g_wvh[256 * 1024];
__device__ __half g_wph[1024 * 1024];

// ---------------- cp.async helpers ----------------
__device__ __forceinline__ void cp16(void* smem_dst, const void* gsrc) {
    uint32_t s = (uint32_t)__cvta_generic_to_shared(smem_dst);
    asm volatile("cp.async.cg.shared.global [%0], [%1], 16;\n" :: "r"(s), "l"(gsrc));
}
#define CP_COMMIT() asm volatile("cp.async.commit_group;\n" ::: "memory")
#define CP_WAIT1()  asm volatile("cp.async.wait_group 1;\n" ::: "memory")
#define CP_WAIT0()  asm volatile("cp.async.wait_group 0;\n" ::: "memory")

__device__ __forceinline__ uint32_t smem_u32(const void* p) {
    return (uint32_t)__cvta_generic_to_shared(p);
}

// ---------------- mma / ldmatrix primitives ----------------
__device__ __forceinline__ void mma16816(float d[4], const uint32_t a[4],
                                         uint32_t b0, uint32_t b1) {
    asm volatile(
        "mma.sync.aligned.m16n8k16.row.col.f32.f16.f16.f32 "
        "{%0,%1,%2,%3}, {%4,%5,%6,%7}, {%8,%9}, {%0,%1,%2,%3};"
        : "+f"(d[0]), "+f"(d[1]), "+f"(d[2]), "+f"(d[3])
        : "r"(a[0]), "r"(a[1]), "r"(a[2]), "r"(a[3]), "r"(b0), "r"(b1));
}
__device__ __forceinline__ void ldm4(uint32_t r[4], uint32_t addr) {
    asm volatile("ldmatrix.sync.aligned.m8n8.x4.shared.b16 {%0,%1,%2,%3}, [%4];"
                 : "=r"(r[0]), "=r"(r[1]), "=r"(r[2]), "=r"(r[3]) : "r"(addr));
}
__device__ __forceinline__ void ldm4t(uint32_t r[4], uint32_t addr) {
    asm volatile("ldmatrix.sync.aligned.m8n8.x4.trans.shared.b16 {%0,%1,%2,%3}, [%4];"
                 : "=r"(r[0]), "=r"(r[1]), "=r"(r[2]), "=r"(r[3]) : "r"(addr));
}

// ---------------- fast exp2 (no MUFU) ----------------
__device__ __forceinline__ float fast_exp2(float x) {
    float t = x + 12582912.0f;
    int   ei = __float_as_int(t) - 0x4B400000;
    float f = x - (t - 12582912.0f);
    float e = fmaf(f, 0.0013333558f, 0.0096181291f);
    e = fmaf(f, e, 0.0555041087f);
    e = fmaf(f, e, 0.2402265070f);
    e = fmaf(f, e, 0.6931471806f);
    e = fmaf(f, e, 1.0f);
    return __int_as_float(__float_as_int(e) + (ei << 23));
}
#define LOG2E_F  1.4426950408889634f
#define NBIAS_F  (-11.541560327111707f)

// ---------------- fused fp16 convert of x + all weights (1 launch) ----------------
#define N4_WQ 262144
#define N4_WK 65536
#define N4_WV 65536
#define N4_WP 262144
__global__ void cvt_all(const float* __restrict__ x,  const float* __restrict__ wq,
                        const float* __restrict__ wk, const float* __restrict__ wv,
                        const float* __restrict__ wp,
                        __half* __restrict__ xo, __half* __restrict__ wqo,
                        __half* __restrict__ wko, __half* __restrict__ wvo,
                        __half* __restrict__ wpo, int n4x) {
    int i = blockIdx.x * blockDim.x + threadIdx.x;
    const float4* s; __half* d; int j;
    if (i < n4x) { s = (const float4*)x; d = xo; j = i; }
    else {
        i -= n4x;
        if (i < N4_WQ)                          { s = (const float4*)wq; d = wqo; j = i; }
        else if (i < N4_WQ + N4_WK)             { s = (const float4*)wk; d = wko; j = i - N4_WQ; }
        else if (i < N4_WQ + N4_WK + N4_WV)     { s = (const float4*)wv; d = wvo; j = i - N4_WQ - N4_WK; }
        else if (i < N4_WQ + N4_WK + N4_WV + N4_WP) { s = (const float4*)wp; d = wpo; j = i - N4_WQ - N4_WK - N4_WV; }
        else return;
    }
    float4 v = s[j];
    __half2 h0 = __floats2half2_rn(v.x, v.y);
    __half2 h1 = __floats2half2_rn(v.z, v.w);
    *reinterpret_cast<__half2*>(&d[j * 4])     = h0;
    *reinterpret_cast<__half2*>(&d[j * 4 + 2]) = h1;
}

// ================= FP16 GEMM, cp.async 3-stage, BK=64 (R13 exact) =================
__device__ __forceinline__ void gemm_core(
    const __half* __restrict__ A, const __half* __restrict__ W,
    float* __restrict__ C, int N, int K, int m0, int n0) {
    extern __shared__ __half smh[];
    __half* As = smh;                          // NSTG * 128 * LDA
    __half* Ws = smh + NSTG * BM * LDA;        // NSTG * 128 * LDA
    const int tid = threadIdx.x;
    const int warp = tid >> 5;
    const int wm = warp >> 2;
    const int wn = warp & 3;

    wmma::fragment<wmma::accumulator, 16, 16, 16, float> acc[4][2];
#pragma unroll
    for (int i = 0; i < 4; i++)
#pragma unroll
        for (int j = 0; j < 2; j++) wmma::fill_fragment(acc[i][j], 0.f);

    const __half* Ab = A + (size_t)m0 * K;
    const __half* Wb = W + (size_t)n0 * K;

#define LOAD_SLAB(it, buf)                                                      \
    {                                                                           \
        const int k0 = (it) << 6;                                               \
        __half* ad = As + (buf) * BM * LDA;                                     \
        __half* wd = Ws + (buf) * BN * LDA;                                     \
        _Pragma("unroll")                                                       \
        for (int i = 0; i < 4; i++) {                                           \
            int ch = tid + i * 256;          /* 0..1023 */                      \
            int r = ch >> 3, c8 = (ch & 7) << 3;                                \
            cp16(ad + r * LDA + c8, Ab + (size_t)r * K + k0 + c8);              \
            cp16(wd + r * LDA + c8, Wb + (size_t)r * K + k0 + c8);              \
        }                                                                       \
    }

    const int nIter = K >> 6;
    LOAD_SLAB(0, 0); CP_COMMIT();
    LOAD_SLAB(1, 1); CP_COMMIT();

    int buf = 0;
    for (int it = 0; it < nIter; ++it) {
        if (it + 1 < nIter) CP_WAIT1(); else CP_WAIT0();
        __syncthreads();
        if (it + 2 < nIter) {
            int nb = buf + 2; if (nb >= NSTG) nb -= NSTG;
            LOAD_SLAB(it + 2, nb); CP_COMMIT();
        }
        const __half* as = As + buf * BM * LDA;
        const __half* ws = Ws + buf * BN * LDA;
#pragma unroll
        for (int kk = 0; kk < BKg; kk += 16) {
            wmma::fragment<wmma::matrix_a, 16, 16, 16, __half, wmma::row_major> a[4];
            wmma::fragment<wmma::matrix_b, 16, 16, 16, __half, wmma::col_major> b[2];
#pragma unroll
            for (int i = 0; i < 4; i++)
                wmma::load_matrix_sync(a[i], &as[(wm * 64 + i * 16) * LDA + kk], LDA);
#pragma unroll
            for (int j = 0; j < 2; j++)
                wmma::load_matrix_sync(b[j], &ws[(wn * 32 + j * 16) * LDA + kk], LDA);
#pragma unroll
            for (int i = 0; i < 4; i++)
#pragma unroll
                for (int j = 0; j < 2; j++)
                    wmma::mma_sync(acc[i][j], a[i], b[j], acc[i][j]);
        }
        if (++buf == NSTG) buf = 0;
    }
#undef LOAD_SLAB
    __syncthreads();
#pragma unroll
    for (int i = 0; i < 4; i++)
#pragma unroll
        for (int j = 0; j < 2; j++)
            wmma::store_matrix_sync(&C[(size_t)(m0 + wm * 64 + i * 16) * N + n0 + wn * 32 + j * 16],
                                    acc[i][j], N, wmma::mem_row_major);
}

__global__ __launch_bounds__(256) void gemm_proj(
    const __half* __restrict__ A, const __half* __restrict__ W, float* __restrict__ C, int K) {
    gemm_core(A, W, C, Ecfg, K, blockIdx.y * BM, blockIdx.x * BN);
}

__global__ __launch_bounds__(256) void gemm_qkv(
    const __half* __restrict__ x,
    const __half* __restrict__ Wq, const __half* __restrict__ Wk, const __half* __restrict__ Wv,
    float* __restrict__ Cq, float* __restrict__ Ck, float* __restrict__ Cv, int K) {
    const int ng = blockIdx.x * BN;
    const __half* W; float* C; int N, n0;
    if (ng < 1024)      { W = Wq; C = Cq; N = 1024; n0 = ng; }
    else if (ng < 1280) { W = Wk; C = Ck; N = 256;  n0 = ng - 1024; }
    else                { W = Wv; C = Cv; N = 256;  n0 = ng - 1280; }
    gemm_core(x, W, C, N, K, blockIdx.y * BM, n0);
}

// ---------------- fused post-QKV: Q rope (y<16) / K rope + V gate (y>=16) ----------------
__global__ void qkv_post_kernel(const float* __restrict__ qraw,
                                const float* __restrict__ kraw,
                                const float* __restrict__ vraw,
                                const float* __restrict__ x,
                                const float* __restrict__ ve,
                                const float* __restrict__ cosb,
                                const float* __restrict__ sinb,
                                const float* __restrict__ Wgate,
                                __half* __restrict__ qt,
                                __half* __restrict__ kt,
                                __half* __restrict__ vt, int T) {
    const int warp = threadIdx.x >> 5, lane = threadIdx.x & 31;
    const int t = blockIdx.x * 8 + warp;
    const int yb = blockIdx.y, b = blockIdx.z;
    const size_t tok = (size_t)b * T + t;

    if (yb < Hh) {
        const int h = yb;
        const float* src = qraw + (tok * Hh + h) * 64;
        float x1 = src[lane], x2 = src[32 + lane];
        float c = cosb[(size_t)t * 32 + lane];
        float s = sinb[(size_t)t * 32 + lane];
        float r1 = x1 * c + x2 * s;
        float r2 = x2 * c - x1 * s;
        float ss = r1 * r1 + r2 * r2;
#pragma unroll
        for (int o = 16; o; o >>= 1) ss += __shfl_xor_sync(0xffffffffu, ss, o);
        float inv = rsqrtf(ss * (1.f / 64.f) + 1.1920929e-07f) * 0.125f;
        __half* d = qt + (((size_t)b * Hh + h) * T + t) * 64;
        d[lane] = __float2half(r1 * inv);
        d[32 + lane] = __float2half(r2 * inv);
    } else {
        const int h = yb - Hh;
        {
            const float* src = kraw + (tok * HKV + h) * 64;
            float x1 = src[lane], x2 = src[32 + lane];
            float c = cosb[(size_t)t * 32 + lane];
            float s = sinb[(size_t)t * 32 + lane];
            float r1 = x1 * c + x2 * s;
            float r2 = x2 * c - x1 * s;
            float ss = r1 * r1 + r2 * r2;
#pragma unroll
            for (int o = 16; o; o >>= 1) ss += __shfl_xor_sync(0xffffffffu, ss, o);
            float inv = rsqrtf(ss * (1.f / 64.f) + 1.1920929e-07f);
            __half* d = kt + (((size_t)b * HKV + h) * T + t) * 64;
            d[lane] = __float2half(r1 * inv);
            d[32 + lane] = __float2half(r2 * inv);
        }
        {
            float g = x[tok * Ecfg + lane] * Wgate[h * 32 + lane];
#pragma unroll
            for (int o = 16; o; o >>= 1) g += __shfl_xor_sync(0xffffffffu, g, o);
            float gate = 2.f / (1.f + __expf(-g));
            const float* vs = vraw + (tok * HKV + h) * 64;
            const float* ves = ve + (tok * HKV + h) * 64;
            __half* d = vt + (((size_t)b * HKV + h) * T + t) * 64;
            d[lane] = __float2half(vs[lane] + gate * ves[lane]);
            d[32 + lane] = __float2half(vs[32 + lane] + gate * ves[32 + lane]);
        }
    }
}

// ================ flash attention: 64-row Q tile, warp owns 16 rows ================
// 128 thr = 4 warps. Halved per-warp register footprint (~100 regs) -> ~5 blocks/SM
// for latency hiding. Per-warp chunk classification as in R16.
__global__ __launch_bounds__(128) void attn_mma(
    const __half* __restrict__ q, const __half* __restrict__ k,
    const __half* __restrict__ v, __half* __restrict__ out,
    const int* __restrict__ wptr, int T) {
    extern __shared__ __half smh[];
    __half* Ks = smh;                  // 2 * 64 * LDK
    __half* Vs = smh + 2 * 64 * LDK;   // 2 * 64 * LDK
    const uint32_t ks0 = smem_u32(Ks);
    const uint32_t vs0 = smem_u32(Vs);

    const int qtile = blockIdx.x, h = blockIdx.y, b = blockIdx.z;
    const int W = wptr[0];
    const int tid = threadIdx.x;
    const int warp = tid >> 5, lane = tid & 31;
    const int qbase = qtile * 64;
    const int rq = lane >> 2;
    const int qc = (lane & 3) << 1;
    const int rowMin = qbase + warp * 16;
    const int rowMax = rowMin + 15;

    const int krow = ((lane >> 4) << 3) + (lane & 7);
    const int kcol = ((lane >> 3) & 1) << 3;
    const int vrow = (((lane >> 3) & 1) << 3) + (lane & 7);
    const int vcol = (lane >> 4) << 3;

    // persistent Q A-fragments: one 16-row strip
    uint32_t qa[4][4];
    {
        const __half* q0 = q + ((size_t)(b * Hh + h) * T + rowMin + rq) * Dd;
        const __half* q8 = q0 + 8 * Dd;
#pragma unroll
        for (int t = 0; t < 4; t++) {
            qa[t][0] = *reinterpret_cast<const uint32_t*>(q0 + t * 16 + qc);
            qa[t][1] = *reinterpret_cast<const uint32_t*>(q8 + t * 16 + qc);
            qa[t][2] = *reinterpret_cast<const uint32_t*>(q0 + t * 16 + 8 + qc);
            qa[t][3] = *reinterpret_cast<const uint32_t*>(q8 + t * 16 + 8 + qc);
        }
    }

    float o[8][4];
#pragma unroll
    for (int j = 0; j < 8; j++)
#pragma unroll
        for (int c = 0; c < 4; c++) o[j][c] = 0.f;
    float lsum[2] = {0.f, 0.f};

    const int hkv = h >> 2;
    const __half* kb = k + (size_t)(b * HKV + hkv) * T * Dd;
    const __half* vb = v + (size_t)(b * HKV + hkv) * T * Dd;
    int kmin = qbase - W; if (kmin < 0) kmin = 0;
    const int t0 = kmin >> 6;
    const int ktend = qtile;

#define LOAD_KV(kt, buf)                                                        \
    {                                                                           \
        const __half* kp = kb + (size_t)(kt) * 64 * Dd;                         \
        const __half* vp = vb + (size_t)(kt) * 64 * Dd;                         \
        __half* kd = Ks + (buf) * 64 * LDK;                                     \
        __half* vd = Vs + (buf) * 64 * LDK;                                     \
        _Pragma("unroll")                                                       \
        for (int i = 0; i < 4; i++) {                                           \
            int ch = tid + i * 128;                                             \
            int r = ch >> 3, c8 = (ch & 7) << 3;                                \
            cp16(kd + r * LDK + c8, kp + r * 64 + c8);                          \
            cp16(vd + r * LDK + c8, vp + r * 64 + c8);                          \
        }                                                                       \
    }

    LOAD_KV(t0, 0); CP_COMMIT();

    for (int kt = t0; kt <= ktend; ++kt) {
        const int buf = (kt - t0) & 1;
        if (kt < ktend) { LOAD_KV(kt + 1, buf ^ 1); CP_COMMIT(); CP_WAIT1(); }
        else CP_WAIT0();
        __syncthreads();
        const uint32_t ksb = ks0 + buf * 64 * LDK * 2;
        const uint32_t vsb = vs0 + buf * 64 * LDK * 2;

#pragma unroll
        for (int t = 0; t < 4; t++) {
            const int chunk0 = (kt << 6) + t * 16;
            if (chunk0 > rowMax) continue;                 // fully future
            if (chunk0 + 15 < rowMin - W) continue;        // fully pre-window
            const bool fullv = (chunk0 + 15 <= rowMin) && (chunk0 >= rowMax - W);

            float s[2][4];
#pragma unroll
            for (int jj = 0; jj < 2; jj++)
#pragma unroll
                for (int c = 0; c < 4; c++) s[jj][c] = 0.f;
#pragma unroll
            for (int kd = 0; kd < 4; kd++) {
                uint32_t kbf[4];
                ldm4(kbf, ksb + (uint32_t)(((t * 16 + krow) * LDK + kd * 16 + kcol) * 2));
                mma16816(s[0], qa[kd], kbf[0], kbf[1]);
                mma16816(s[1], qa[kd], kbf[2], kbf[3]);
            }
            uint32_t pa[4];
            if (fullv) {
#pragma unroll
                for (int jj = 0; jj < 2; jj++) {
#pragma unroll
                    for (int c = 0; c < 4; c++) {
                        float pv = fast_exp2(fmaf(s[jj][c], LOG2E_F, NBIAS_F));
                        lsum[c >> 1] += pv;
                        s[jj][c] = pv;
                    }
                    __half2 lo = __floats2half2_rn(s[jj][0], s[jj][1]);
                    __half2 hi = __floats2half2_rn(s[jj][2], s[jj][3]);
                    pa[jj * 2 + 0] = *reinterpret_cast<uint32_t*>(&lo);
                    pa[jj * 2 + 1] = *reinterpret_cast<uint32_t*>(&hi);
                }
            } else {
                const int row0 = rowMin + rq;
#pragma unroll
                for (int jj = 0; jj < 2; jj++) {
                    const int colb = chunk0 + jj * 8 + qc;
#pragma unroll
                    for (int c = 0; c < 4; c++) {
                        const int row = row0 + ((c >> 1) << 3);
                        const int col = colb + (c & 1);
                        float pv = 0.f;
                        if (col <= row && col >= row - W) {
                            pv = fast_exp2(fmaf(s[jj][c], LOG2E_F, NBIAS_F));
                            lsum[c >> 1] += pv;
                        }
                        s[jj][c] = pv;
                    }
                    __half2 lo = __floats2half2_rn(s[jj][0], s[jj][1]);
                    __half2 hi = __floats2half2_rn(s[jj][2], s[jj][3]);
                    pa[jj * 2 + 0] = *reinterpret_cast<uint32_t*>(&lo);
                    pa[jj * 2 + 1] = *reinterpret_cast<uint32_t*>(&hi);
                }
            }
#pragma unroll
            for (int jdp = 0; jdp < 4; jdp++) {
                uint32_t vbf[4];
                ldm4t(vbf, vsb + (uint32_t)(((t * 16 + vrow) * LDK + jdp * 16 + vcol) * 2));
                mma16816(o[jdp * 2 + 0], pa, vbf[0], vbf[1]);
                mma16816(o[jdp * 2 + 1], pa, vbf[2], vbf[3]);
            }
        }
        __syncthreads();
    }
#undef LOAD_KV

#pragma unroll
    for (int rh = 0; rh < 2; rh++) {
        float l = lsum[rh];
        l += __shfl_xor_sync(0xffffffffu, l, 1);
        l += __shfl_xor_sync(0xffffffffu, l, 2);
        const float inv = 1.f / l;
        const int qrow = rowMin + rq + rh * 8;
        __half* op = out + ((size_t)(b * T + qrow) * Hh + h) * Dd + qc;
#pragma unroll
        for (int jd = 0; jd < 8; jd++) {
            __half2 hv = __floats2half2_rn(o[jd][rh * 2] * inv,
                                           o[jd][rh * 2 + 1] * inv);
            *reinterpret_cast<__half2*>(op + jd * 8) = hv;
        }
    }
}

// ---------------- launch ----------------
extern "C" void kernel_launch(void* const* d_in, const int* in_sizes, int n_in,
                              void* d_out, int out_size) {
    const float* x     = (const float*)d_in[0];
    const float* ve    = (const float*)d_in[1];
    const float* cosb  = (const float*)d_in[2];
    const float* sinb  = (const float*)d_in[3];
    const float* Wq    = (const float*)d_in[4];
    const float* Wk    = (const float*)d_in[5];
    const float* Wv    = (const float*)d_in[6];
    const float* Wproj = (const float*)d_in[7];
    const float* Wgate = (const float*)d_in[8];
    const int*   wsz   = (const int*)d_in[9];

    int T = in_sizes[2] / 32;
    int B = in_sizes[0] / (T * Ecfg);
    int M = B * T;

    float *qraw, *kraw, *vraw;
    __half *qt, *kt, *vt, *y, *xh, *wqh, *wkh, *wvh, *wph;
    cudaGetSymbolAddress((void**)&qraw, g_qraw);
    cudaGetSymbolAddress((void**)&kraw, g_kraw);
    cudaGetSymbolAddress((void**)&vraw, g_vraw);
    cudaGetSymbolAddress((void**)&qt,   g_qt);
    cudaGetSymbolAddress((void**)&kt,   g_kt);
    cudaGetSymbolAddress((void**)&vt,   g_vt);
    cudaGetSymbolAddress((void**)&y,    g_y);
    cudaGetSymbolAddress((void**)&xh,   g_xh);
    cudaGetSymbolAddress((void**)&wqh,  g_wqh);
    cudaGetSymbolAddress((void**)&wkh,  g_wkh);
    cudaGetSymbolAddress((void**)&wvh,  g_wvh);
    cudaGetSymbolAddress((void**)&wph,  g_wph);

    const int gemm_smem = NSTG * (BM + BN) * LDA * 2;   // 110592
    const int attn_smem = 4 * 64 * LDK * 2;             // 36864
    cudaFuncSetAttribute(gemm_qkv,  cudaFuncAttributeMaxDynamicSharedMemorySize, gemm_smem);
    cudaFuncSetAttribute(gemm_proj, cudaFuncAttributeMaxDynamicSharedMemorySize, gemm_smem);
    cudaFuncSetAttribute(attn_mma,  cudaFuncAttributeMaxDynamicSharedMemorySize, attn_smem);

    {
        int n4x = M * Ecfg / 4;
        int total = n4x + N4_WQ + N4_WK + N4_WV + N4_WP;
        cvt_all<<<(total + 255) / 256, 256>>>(x, Wq, Wk, Wv, Wproj,
                                              xh, wqh, wkh, wvh, wph, n4x);
    }

    gemm_qkv<<<dim3(1536 / BN, M / BM), 256, gemm_smem>>>(xh, wqh, wkh, wvh, qraw, kraw, vraw, Ecfg);

    qkv_post_kernel<<<dim3(T / 8, Hh + HKV, B), 256>>>(qraw, kraw, vraw, x, ve,
                                                       cosb, sinb, Wgate, qt, kt, vt, T);

    attn_mma<<<dim3(T / 64, Hh, B), 128, attn_smem>>>(qt, kt, vt, y, wsz, T);

    gemm_proj<<<dim3(Ecfg / BN, M / BM), 256, gemm_smem>>>(y, wph, (float*)d_out, Ecfg);
}